// round 5
// baseline (speedup 1.0000x reference)
#include <cuda_runtime.h>
#include <cuda_fp16.h>
#include <math.h>

// ---------------- problem constants ----------------
#define Bn   16
#define Cf   64
#define Ll   16384        // H*W
#define Gg   8
#define DI   16           // D_INNER
#define DS   16           // D_STATE
#define NH   2
#define HD   8
#define CDIM 48           // DI + 2*DS
#define DIP  66
#define Q    32           // chunk length (exp(|cld|) stays finite in fp32)
#define NCHs 512          // chunks per sequence = Ll/Q
#define BL   (Bn*Ll)      // 262144

// ---------------- scratch (static device globals; no allocs) ----------------
__device__ __align__(16) __half  g_gt [BL*Gg];     // tokenized seq (residual), fp16
__device__ __align__(16) __half  g_xBC[BL*CDIM];   // [l][ x(16) | B(16) | C(16) ] fp16
__device__ __align__(16) __half  g_zs [BL*DI];     // silu(z) fp16
__device__ __align__(16) __half  g_yi [BL*DI];     // intra-chunk y, [l][h*8+p] fp16
__device__ __align__(16) float4  g_dtla[BL];       // (dt0, dt1, dla0, dla1)
__device__ __align__(16) float2  g_E  [BL];        // exp(cld) per head
__device__ __align__(16) float   g_S  [Bn*NH*NCHs*128];  // chunk-produced state
__device__ __align__(16) float   g_hs [Bn*NH*NCHs*128];  // state entering chunk
__device__ __align__(16) float   g_ct [Bn*NH*NCHs];      // exp(chunk total log-decay)

// ---------------- fp16 pack helpers ----------------
union H8u { __half2 h2[4]; uint4 u4; };
__device__ __forceinline__ void st_h8(__half* p, const float* v) {
    H8u k;
    k.h2[0] = __floats2half2_rn(v[0], v[1]);
    k.h2[1] = __floats2half2_rn(v[2], v[3]);
    k.h2[2] = __floats2half2_rn(v[4], v[5]);
    k.h2[3] = __floats2half2_rn(v[6], v[7]);
    *(uint4*)p = k.u4;
}
__device__ __forceinline__ void ld_h8(const __half* p, float* v) {
    H8u k; k.u4 = *(const uint4*)p;
    float2 f;
    f = __half22float2(k.h2[0]); v[0] = f.x; v[1] = f.y;
    f = __half22float2(k.h2[1]); v[2] = f.x; v[3] = f.y;
    f = __half22float2(k.h2[2]); v[4] = f.x; v[5] = f.y;
    f = __half22float2(k.h2[3]); v[6] = f.x; v[7] = f.y;
}

// ======================================================================
// K1: tokenize + in_proj + depthwise causal conv(3) + silu + softplus(dt)
// block = 128 threads = 128 consecutive l. grid (Ll/128, B)
// ======================================================================
__global__ void __launch_bounds__(128) k_front(
    const float* __restrict__ x,  const float* __restrict__ tw, const float* __restrict__ tb,
    const float* __restrict__ ipw, const float* __restrict__ ipb,
    const float* __restrict__ cw,  const float* __restrict__ cb,
    const float* __restrict__ Alog, const float* __restrict__ dtb)
{
    __shared__ float gsh[130][9];       // gt rows (2-row halo, odd stride: conflict-free)
    __shared__ float xbc[130][49];      // pre-conv xBC (odd stride)
    __shared__ float stw[Cf*Gg];        // tok weights transposed [c][g]
    __shared__ float stb[Gg];
    __shared__ float wip[DIP*Gg];
    __shared__ float bip[DIP];
    __shared__ float wcv[CDIM*3];
    __shared__ float bcv[CDIM];
    __shared__ float sA[NH], sdtb[NH];

    int tid = threadIdx.x;
    for (int i = tid; i < Cf*Gg; i += 128) { int c = i >> 3, g = i & 7; stw[i] = tw[g*Cf + c]; }
    for (int i = tid; i < DIP*Gg; i += 128) wip[i] = ipw[i];
    for (int i = tid; i < DIP;    i += 128) bip[i] = ipb[i];
    for (int i = tid; i < CDIM*3; i += 128) wcv[i] = cw[i];
    for (int i = tid; i < CDIM;   i += 128) bcv[i] = cb[i];
    if (tid < Gg) stb[tid] = tb[tid];
    if (tid < NH) { sA[tid] = __expf(Alog[tid]); sdtb[tid] = dtb[tid]; }
    __syncthreads();

    int b = blockIdx.y, l0 = blockIdx.x * 128;

    // ---- tokenize rows l0-2 .. l0+127 (each l stored exactly once) ----
    for (int r = tid; r < 130; r += 128) {
        int l = l0 + r - 2;
        float acc[8];
        if (l >= 0) {
            #pragma unroll
            for (int g = 0; g < 8; g++) acc[g] = stb[g];
            const float* xp = x + (size_t)b*Cf*Ll + l;
            #pragma unroll 8
            for (int c = 0; c < Cf; c++) {
                float v = xp[(size_t)c*Ll];
                const float* wr = stw + c*8;
                #pragma unroll
                for (int g = 0; g < 8; g++) acc[g] += v * wr[g];
            }
        } else {
            #pragma unroll
            for (int g = 0; g < 8; g++) acc[g] = 0.f;
        }
        #pragma unroll
        for (int g = 0; g < 8; g++) gsh[r][g] = acc[g];
        if (r >= 2) st_h8(g_gt + ((size_t)b*Ll + l)*8, acc);
    }
    __syncthreads();

    // ---- pre-conv xBC (conv zero-pads its INPUT at l<0) ----
    for (int r = tid; r < 130; r += 128) {
        float gv[8];
        #pragma unroll
        for (int g = 0; g < 8; g++) gv[g] = gsh[r][g];
        int l = l0 + r - 2;
        #pragma unroll 4
        for (int j = 0; j < CDIM; j++) {
            float a = bip[DI + j];
            #pragma unroll
            for (int g = 0; g < 8; g++) a += gv[g] * wip[(DI + j)*8 + g];
            xbc[r][j] = (l >= 0) ? a : 0.f;
        }
    }
    __syncthreads();

    int l = l0 + tid;
    size_t base = (size_t)b*Ll + l;
    float gv[8];
    #pragma unroll
    for (int g = 0; g < 8; g++) gv[g] = gsh[tid + 2][g];

    // z -> silu(z)
    float z[DI];
    #pragma unroll
    for (int j = 0; j < DI; j++) {
        float a = bip[j];
        #pragma unroll
        for (int g = 0; g < 8; g++) a += gv[g] * wip[j*8 + g];
        z[j] = a / (1.f + __expf(-a));
    }
    st_h8(g_zs + base*DI, z);
    st_h8(g_zs + base*DI + 8, z + 8);

    // dt heads: softplus(dt + dt_bias), log-decay = -dt*exp(A_log)
    float dts[2], dlas[2];
    #pragma unroll
    for (int h = 0; h < NH; h++) {
        float a = bip[DI + CDIM + h];
        #pragma unroll
        for (int g = 0; g < 8; g++) a += gv[g] * wip[(DI + CDIM + h)*8 + g];
        a += sdtb[h];
        float dt = (a > 20.f) ? a : log1pf(__expf(a));
        dts[h] = dt; dlas[h] = -dt * sA[h];
    }
    g_dtla[base] = make_float4(dts[0], dts[1], dlas[0], dlas[1]);

    // causal conv(3) + silu:  out[l] = w0*in[l-2] + w1*in[l-1] + w2*in[l]
    float v48[CDIM];
    #pragma unroll 4
    for (int j = 0; j < CDIM; j++) {
        float v = xbc[tid][j]   * wcv[j*3 + 0]
                + xbc[tid+1][j] * wcv[j*3 + 1]
                + xbc[tid+2][j] * wcv[j*3 + 2]
                + bcv[j];
        v48[j] = v / (1.f + __expf(-v));
    }
    __half* xo = g_xBC + base*CDIM;
    st_h8(xo,      v48);      st_h8(xo + 8,  v48 + 8);
    st_h8(xo + 16, v48 + 16); st_h8(xo + 24, v48 + 24);
    st_h8(xo + 32, v48 + 32); st_h8(xo + 40, v48 + 40);
}

// ======================================================================
// K2: intra-chunk SSD, Q=32, one warp per chunk, BOTH heads per warp
// (B/C are head-independent: the 16-FMA C_t.B_s dot is shared).
// block = 128 (4 warps = 4 chunks). grid (NCHs/4, B)
// y_t = sum_{s<=t} exp(cld_t - cld_s) * dt_s * (C_t.B_s) * x_s
// ======================================================================
__global__ void __launch_bounds__(128) k_chunk()
{
    __shared__ float4 sB[4][4][32];   // [warp][quad][s]
    __shared__ float4 sx[4][4][32];   // [warp][quad][s]  (quads 0-1 head0, 2-3 head1)
    __shared__ float2 su[4][32];      // dt*exp(-cld) per head
    __shared__ float2 sv[4][32];      // dt*exp(cl_end - cld) per head

    int tid = threadIdx.x, w = tid >> 5, lane = tid & 31;
    int b = blockIdx.y;
    int c = blockIdx.x * 4 + w;
    int l = c * Q + lane;
    size_t base = (size_t)b*Ll + l;

    const __half* xb = g_xBC + base*CDIM;
    float xv[16], bv[16];
    ld_h8(xb,      xv); ld_h8(xb + 8,  xv + 8);
    ld_h8(xb + 16, bv); ld_h8(xb + 24, bv + 8);
    #pragma unroll
    for (int q = 0; q < 4; q++) {
        sx[w][q][lane] = make_float4(xv[q*4], xv[q*4+1], xv[q*4+2], xv[q*4+3]);
        sB[w][q][lane] = make_float4(bv[q*4], bv[q*4+1], bv[q*4+2], bv[q*4+3]);
    }

    float4 dl = g_dtla[base];
    float c0 = dl.z, c1 = dl.w;
    // warp-inclusive scan of log-decay (both heads)
    #pragma unroll
    for (int off = 1; off < 32; off <<= 1) {
        float t0 = __shfl_up_sync(0xffffffffu, c0, off);
        float t1 = __shfl_up_sync(0xffffffffu, c1, off);
        if (lane >= off) { c0 += t0; c1 += t1; }
    }
    float E0 = __expf(c0), E1 = __expf(c1);
    g_E[base] = make_float2(E0, E1);
    su[w][lane] = make_float2(dl.x * __expf(-c0), dl.y * __expf(-c1));
    float cl0 = __shfl_sync(0xffffffffu, c0, 31);
    float cl1 = __shfl_sync(0xffffffffu, c1, 31);
    sv[w][lane] = make_float2(dl.x * __expf(cl0 - c0), dl.y * __expf(cl1 - c1));

    float cv[16];
    ld_h8(xb + 32, cv); ld_h8(xb + 40, cv + 8);
    __syncwarp();

    // ---- triangular intra-chunk y (both heads share the dot) ----
    float acc[16];
    #pragma unroll
    for (int i = 0; i < 16; i++) acc[i] = 0.f;
    #pragma unroll 4
    for (int s = 0; s < Q; s++) {
        float4 B0 = sB[w][0][s], B1 = sB[w][1][s], B2 = sB[w][2][s], B3 = sB[w][3][s];
        float dot = cv[0]*B0.x + cv[1]*B0.y + cv[2]*B0.z + cv[3]*B0.w
                  + cv[4]*B1.x + cv[5]*B1.y + cv[6]*B1.z + cv[7]*B1.w
                  + cv[8]*B2.x + cv[9]*B2.y + cv[10]*B2.z + cv[11]*B2.w
                  + cv[12]*B3.x + cv[13]*B3.y + cv[14]*B3.z + cv[15]*B3.w;
        if (s <= lane) {
            float2 uu = su[w][s];
            float w0 = E0 * uu.x * dot, w1 = E1 * uu.y * dot;   // = exp(cld_t-cld_s)*dt_s*dot
            float4 X0 = sx[w][0][s], X1 = sx[w][1][s], X2 = sx[w][2][s], X3 = sx[w][3][s];
            acc[0] += w0*X0.x; acc[1] += w0*X0.y; acc[2]  += w0*X0.z; acc[3]  += w0*X0.w;
            acc[4] += w0*X1.x; acc[5] += w0*X1.y; acc[6]  += w0*X1.z; acc[7]  += w0*X1.w;
            acc[8] += w1*X2.x; acc[9] += w1*X2.y; acc[10] += w1*X2.z; acc[11] += w1*X2.w;
            acc[12]+= w1*X3.x; acc[13]+= w1*X3.y; acc[14] += w1*X3.z; acc[15] += w1*X3.w;
        }
    }
    st_h8(g_yi + base*DI,     acc);
    st_h8(g_yi + base*DI + 8, acc + 8);

    // ---- chunk summary S[h][n][p] = sum_s v_{s,h} * B_s[n] * x_{s,h}[p] ----
    // lane = nb*8+p, n = 4j+nb  =>  flat (n*8+p) == lane + 32j  (coalesced stores)
    int nb = lane >> 3, p = lane & 7;
    const float* sBf = (const float*)&sB[w][0][0];
    const float* sxf = (const float*)&sx[w][0][0];
    float s8[8];
    #pragma unroll
    for (int i = 0; i < 8; i++) s8[i] = 0.f;
    #pragma unroll 4
    for (int s = 0; s < Q; s++) {
        float2 vv = sv[w][s];
        float x0 = sxf[(p >> 2)*128 + s*4 + (p & 3)];          // head0 x[s][p]
        float x1 = sxf[(2 + (p >> 2))*128 + s*4 + (p & 3)];    // head1 x[s][p]
        float t0 = vv.x * x0, t1 = vv.y * x1;
        #pragma unroll
        for (int j = 0; j < 4; j++) {
            float Bv = sBf[j*128 + s*4 + nb];                  // B[s][4j+nb]
            s8[j]     += t0 * Bv;
            s8[4 + j] += t1 * Bv;
        }
    }
    size_t i0 = ((size_t)(b*2 + 0)*NCHs + c) * 128;
    size_t i1 = ((size_t)(b*2 + 1)*NCHs + c) * 128;
    #pragma unroll
    for (int j = 0; j < 4; j++) {
        g_S[i0 + lane + 32*j] = s8[j];
        g_S[i1 + lane + 32*j] = s8[4 + j];
    }
    if (lane == 0) {
        // store the READY decay factor exp(cl): moves 512 serial MUFU exps
        // out of k_scan's (occupancy-starved) critical path.
        g_ct[(b*2 + 0)*NCHs + c] = __expf(cl0);
        g_ct[(b*2 + 1)*NCHs + c] = __expf(cl1);
    }
}

// ======================================================================
// K3: sequential scan over chunks. grid 32 = (b,h), 128 threads = (n,p)
// h_enter[c+1] = A[c] * h_enter[c] + S[c],  A = exp(ct) precomputed in K2.
// Double-buffered register tiles (TS=16): the 16 loads of tile t+1 issue
// as an independent batch BEFORE tile t's FMA chain runs, structurally
// guaranteeing ~1 tile of latency slack + MLP=16 per load batch.
// ======================================================================
#define TS 16
__global__ void __launch_bounds__(128) k_scan()
{
    int bh = blockIdx.x;
    int j = threadIdx.x;
    size_t base = (size_t)bh * NCHs;

    float Sb[2][TS], Ab[2][TS];

    // preload tile 0
    #pragma unroll
    for (int r = 0; r < TS; r++) {
        Sb[0][r] = g_S[(base + r)*128 + j];
        Ab[0][r] = g_ct[base + r];
    }

    float hv = 0.f;
    #pragma unroll 1
    for (int t = 0; t < NCHs/TS; t++) {
        int cur = t & 1, nxt = cur ^ 1;
        if (t + 1 < NCHs/TS) {
            size_t nb = base + (size_t)(t + 1)*TS;
            #pragma unroll
            for (int r = 0; r < TS; r++) {
                Sb[nxt][r] = g_S[(nb + r)*128 + j];   // independent of hv chain
                Ab[nxt][r] = g_ct[nb + r];
            }
        }
        size_t cb = base + (size_t)t*TS;
        #pragma unroll
        for (int r = 0; r < TS; r++) {
            g_hs[(cb + r)*128 + j] = hv;
            hv = Ab[cur][r]*hv + Sb[cur][r];          // 4-cyc dependent FMA
        }
    }
}

// ======================================================================
// K4: inter-chunk y + D*x + gate + RMSNorm + out_proj + residual
//     + detokenize + final residual (writes d_out directly).
// block = 128 threads = 128 l (4 chunks). grid (Ll/128, B)
// ======================================================================
__global__ void __launch_bounds__(128) k_back(
    const float* __restrict__ Dv, const float* __restrict__ nw,
    const float* __restrict__ ow, const float* __restrict__ ob,
    const float* __restrict__ x,  const float* __restrict__ dw,
    const float* __restrict__ db, float* __restrict__ out)
{
    __shared__ float hs[4][2][128];
    __shared__ float sow[Gg*DI], sob[Gg], snw[DI], sD[NH];
    __shared__ float sdw[Cf*Gg], sdb[Cf];

    int tid = threadIdx.x;
    int b = blockIdx.y, l0 = blockIdx.x * 128;
    for (int i = tid; i < Gg*DI; i += 128) sow[i] = ow[i];
    for (int i = tid; i < Cf*Gg; i += 128) sdw[i] = dw[i];
    if (tid < Cf) sdb[tid] = db[tid];
    if (tid < Gg) sob[tid] = ob[tid];
    if (tid < DI) snw[tid] = nw[tid];
    if (tid < NH) sD[tid]  = Dv[tid];
    int c0 = l0 >> 5;
    for (int i = tid; i < 4*2*128; i += 128) {
        int cc = i >> 8, rem = i & 255, h = rem >> 7, j = rem & 127;
        hs[cc][h][j] = g_hs[(((size_t)(b*2 + h))*NCHs + c0 + cc)*128 + j];
    }
    __syncthreads();

    int w = tid >> 5;
    int l = l0 + tid;
    size_t base = (size_t)b*Ll + l;

    const __half* xbp = g_xBC + base*CDIM;
    float cv[16], xv[16], yv[16], zv[16], gv[8];
    ld_h8(xbp + 32, cv); ld_h8(xbp + 40, cv + 8);
    ld_h8(xbp,      xv); ld_h8(xbp + 8,  xv + 8);
    ld_h8(g_yi + base*DI, yv); ld_h8(g_yi + base*DI + 8, yv + 8);
    ld_h8(g_zs + base*DI, zv); ld_h8(g_zs + base*DI + 8, zv + 8);
    float2 E = g_E[base];
    ld_h8(g_gt + base*8, gv);

    // y = y_intra + exp(cld)*C.h_enter + D*x   (warp-uniform hs reads: broadcast)
    float y[16];
    #pragma unroll
    for (int h = 0; h < 2; h++) {
        float Eh = (h == 0) ? E.x : E.y;
        #pragma unroll
        for (int p = 0; p < 8; p++) {
            float inter = 0.f;
            #pragma unroll
            for (int n = 0; n < 16; n++) inter += cv[n] * hs[w][h][n*8 + p];
            y[h*8 + p] = yv[h*8 + p] + Eh * inter + sD[h] * xv[h*8 + p];
        }
    }

    // gate + RMSNorm
    float ms = 0.f;
    #pragma unroll
    for (int i = 0; i < 16; i++) {
        y[i] *= zv[i];
        ms += y[i] * y[i];
    }
    float r = rsqrtf(ms * (1.f/16.f) + 1e-5f);
    #pragma unroll
    for (int i = 0; i < 16; i++) y[i] *= r * snw[i];

    // out_proj + sequence residual
    float og[8];
    #pragma unroll
    for (int g = 0; g < 8; g++) {
        float a = sob[g];
        #pragma unroll
        for (int i = 0; i < 16; i++) a += y[i] * sow[g*16 + i];
        og[g] = a + gv[g];
    }

    // detokenize + final residual
    const float* xp = x   + (size_t)b*Cf*Ll + l;
    float*       op = out + (size_t)b*Cf*Ll + l;
    #pragma unroll 8
    for (int cch = 0; cch < Cf; cch++) {
        const float* wr = sdw + cch*8;
        float a = sdb[cch]
            + og[0]*wr[0] + og[1]*wr[1] + og[2]*wr[2] + og[3]*wr[3]
            + og[4]*wr[4] + og[5]*wr[5] + og[6]*wr[6] + og[7]*wr[7];
        op[(size_t)cch*Ll] = xp[(size_t)cch*Ll] + a;
    }
}

// ======================================================================
extern "C" void kernel_launch(void* const* d_in, const int* in_sizes, int n_in,
                              void* d_out, int out_size) {
    const float* x         = (const float*)d_in[0];
    const float* tok_w     = (const float*)d_in[1];
    const float* tok_b     = (const float*)d_in[2];
    const float* detok_w   = (const float*)d_in[3];
    const float* detok_b   = (const float*)d_in[4];
    const float* in_proj_w = (const float*)d_in[5];
    const float* in_proj_b = (const float*)d_in[6];
    const float* conv_w    = (const float*)d_in[7];
    const float* conv_b    = (const float*)d_in[8];
    const float* A_log     = (const float*)d_in[9];
    const float* Dv        = (const float*)d_in[10];
    const float* dt_bias   = (const float*)d_in[11];
    const float* norm_w    = (const float*)d_in[12];
    const float* out_w     = (const float*)d_in[13];
    const float* out_b     = (const float*)d_in[14];
    float* out = (float*)d_out;

    k_front<<<dim3(Ll/128, Bn), 128>>>(x, tok_w, tok_b, in_proj_w, in_proj_b,
                                       conv_w, conv_b, A_log, dt_bias);
    k_chunk<<<dim3(NCHs/4, Bn), 128>>>();
    k_scan <<<Bn*NH, 128>>>();
    k_back <<<dim3(Ll/128, Bn), 128>>>(Dv, norm_w, out_w, out_b,
                                       x, detok_w, detok_b, out);
}